// round 8
// baseline (speedup 1.0000x reference)
#include <cuda_runtime.h>
#include <cstdint>

#define NH   4096
#define NN   16384
#define DD   1024
#define EHH  8192
#define EOO  40960
#define EE   65536

// ---------------- GEMM tile config ----------------
#define BM      128
#define BN      256
#define BK      32
#define STAGES  3
#define LDP     (BK + 4)                     // padded row stride (floats)
#define A_STAGE_BYTES (BM * LDP * 4)         // 18432
#define STAGE_BYTES   ((BM + BN) * LDP * 4)  // 55296
#define DYN_SMEM (STAGES * STAGE_BYTES)      // 165888

// ---------------- scratch (__device__ globals; no allocs allowed) ----------
__device__ float g_A[(size_t)3 * NN * DD];      // A_t = n_f @ W_t[:D]
__device__ float g_B[(size_t)3 * NN * DD];      // B_t = n_f @ W_t[D:]
__device__ float g_z[(size_t)NN * DD];          // z_f accumulator (fp32 -> tf32)
__device__ float g_nf[(size_t)NN * DD];         // tf32-rounded copy of n_f
__device__ float g_ex[EE];                      // exp(logit)
__device__ float g_den[NN];                     // softmax denominators
__device__ float g_Wp[(size_t)6 * DD * DD];     // 6 proj weights, transposed [N,K], tf32
__device__ float g_Wn[(size_t)2 * DD * 2 * DD]; // 2 node weights, transposed [N,2K], tf32

// ---------------- helpers ---------------------------------------------------
__device__ __forceinline__ float to_tf32(float x) {
    uint32_t o;
    asm("cvt.rna.tf32.f32 %0, %1;" : "=r"(o) : "f"(x));
    return __uint_as_float(o);
}
__device__ __forceinline__ uint32_t smem_u32(const void* p) {
    uint32_t a;
    asm("{ .reg .u64 t; cvta.to.shared.u64 t, %1; cvt.u32.u64 %0, t; }"
        : "=r"(a) : "l"(p));
    return a;
}
__device__ __forceinline__ void cp_async16(uint32_t dst, const void* src) {
    asm volatile("cp.async.cg.shared.global [%0], [%1], 16;"
                 :: "r"(dst), "l"(src) : "memory");
}
#define CP_COMMIT()  asm volatile("cp.async.commit_group;" ::: "memory")
#define CP_WAIT1()   asm volatile("cp.async.wait_group 1;" ::: "memory")

__device__ __forceinline__ void mma8(float* c, const float* a, const float* b) {
    asm volatile(
        "mma.sync.aligned.m16n8k8.row.col.f32.tf32.tf32.f32 "
        "{%0,%1,%2,%3}, {%4,%5,%6,%7}, {%8,%9}, {%0,%1,%2,%3};"
        : "+f"(c[0]), "+f"(c[1]), "+f"(c[2]), "+f"(c[3])
        : "r"(__float_as_uint(a[0])), "r"(__float_as_uint(a[1])),
          "r"(__float_as_uint(a[2])), "r"(__float_as_uint(a[3])),
          "r"(__float_as_uint(b[0])), "r"(__float_as_uint(b[1])));
}

// ---------------------------------------------------------------------------
__global__ void k_zero() {
    size_t i = (size_t)blockIdx.x * blockDim.x + threadIdx.x;
    g_z[i] = 0.f;
    if (i < NN) g_den[i] = 0.f;
}

// round n_f -> g_nf (tf32 quantization done once, not per-fragment)
__global__ void k_cvt_nf(const float* __restrict__ src) {
    size_t i = (size_t)blockIdx.x * blockDim.x + threadIdx.x;
    float4 v = ((const float4*)src)[i];
    v.x = to_tf32(v.x); v.y = to_tf32(v.y); v.z = to_tf32(v.z); v.w = to_tf32(v.w);
    ((float4*)g_nf)[i] = v;
}
// round g_z in place after scatter
__global__ void k_round_z() {
    size_t i = (size_t)blockIdx.x * blockDim.x + threadIdx.x;
    float4 v = ((float4*)g_z)[i];
    v.x = to_tf32(v.x); v.y = to_tf32(v.y); v.z = to_tf32(v.z); v.w = to_tf32(v.w);
    ((float4*)g_z)[i] = v;
}

// transpose + tf32 round: dst[n*K + k] = tf32(src[k*Nn + n])
__global__ void k_transpose(const float* __restrict__ src, float* __restrict__ dst,
                            int K, int Nn) {
    __shared__ float t[32][33];
    const int k0 = blockIdx.x * 32, n0 = blockIdx.y * 32;
    const int x = threadIdx.x, y = threadIdx.y;
#pragma unroll
    for (int i = y; i < 32; i += 8)
        t[i][x] = src[(size_t)(k0 + i) * Nn + n0 + x];
    __syncthreads();
#pragma unroll
    for (int i = y; i < 32; i += 8)
        dst[(size_t)(n0 + i) * K + k0 + x] = to_tf32(t[x][i]);
}

// ---------------------------------------------------------------------------
// tf32 mma.sync GEMM: C[BMxBN tile] = A[rowBase:, :K] @ W^T[colBase:, :K]
// A0 for k<DD, A1 for k>=DD (both ld=DD). W is [N,K] row-major, ld=ldB.
// 8 warps in 2(M) x 4(N); each warp computes 64x64.
__device__ __forceinline__ void gemm_body(
    char* smem, int tid,
    const float* A0, const float* A1, const float* W, int ldB, int K,
    int rowBase, int colBase, float* outp, const float* bias, bool relu)
{
    const int lane = tid & 31, wid = tid >> 5;
    const int grp = lane >> 2, t4 = lane & 3;
    const int wm = wid >> 2, wn = wid & 3;

    const uint32_t sb = smem_u32(smem);
    const int vr = tid >> 3;            // vector row base (0..31)
    const int kv = (tid & 7) * 4;       // k offset of 16B vector

    const int KT = K / BK;

    // prefetch one stage: A 128 rows, B 256 rows
    auto prefetch = [&](int st, int kt) {
        const int k0 = kt * BK;
        const float* Asrc = (k0 < DD) ? A0 : A1;
        const int kk = (k0 < DD) ? k0 : k0 - DD;
        const uint32_t sA = sb + st * STAGE_BYTES;
        const uint32_t sB = sA + A_STAGE_BYTES;
#pragma unroll
        for (int i = 0; i < 4; i++) {
            const int r = vr + i * 32;
            cp_async16(sA + (uint32_t)(r * LDP + kv) * 4,
                       Asrc + (size_t)(rowBase + r) * DD + kk + kv);
        }
#pragma unroll
        for (int i = 0; i < 8; i++) {
            const int r = vr + i * 32;
            cp_async16(sB + (uint32_t)(r * LDP + kv) * 4,
                       W + (size_t)(colBase + r) * ldB + k0 + kv);
        }
        CP_COMMIT();
    };

    prefetch(0, 0);
    prefetch(1, 1);

    float acc[4][8][4] = {};

    for (int kt = 0; kt < KT; kt++) {
        CP_WAIT1();
        __syncthreads();
        if (kt + 2 < KT) prefetch((kt + 2) % STAGES, kt + 2);
        else CP_COMMIT();                       // keep group count consistent

        const int st = kt % STAGES;
        const float* As = (const float*)(smem + st * STAGE_BYTES);
        const float* Bs = (const float*)(smem + st * STAGE_BYTES + A_STAGE_BYTES);

#pragma unroll
        for (int ks = 0; ks < 4; ks++) {
            const int kb = ks * 8;
            float a[4][4], b[8][2];
#pragma unroll
            for (int mi = 0; mi < 4; mi++) {
                const int r0 = wm * 64 + mi * 16 + grp;
                a[mi][0] = As[(r0    ) * LDP + kb + t4    ];
                a[mi][1] = As[(r0 + 8) * LDP + kb + t4    ];
                a[mi][2] = As[(r0    ) * LDP + kb + t4 + 4];
                a[mi][3] = As[(r0 + 8) * LDP + kb + t4 + 4];
            }
#pragma unroll
            for (int ni = 0; ni < 8; ni++) {
                const int c0 = wn * 64 + ni * 8 + grp;
                b[ni][0] = Bs[c0 * LDP + kb + t4    ];
                b[ni][1] = Bs[c0 * LDP + kb + t4 + 4];
            }
#pragma unroll
            for (int mi = 0; mi < 4; mi++)
#pragma unroll
                for (int ni = 0; ni < 8; ni++)
                    mma8(acc[mi][ni], a[mi], b[ni]);
        }
    }

    // epilogue
#pragma unroll
    for (int mi = 0; mi < 4; mi++) {
#pragma unroll
        for (int ni = 0; ni < 8; ni++) {
            const int row = rowBase + wm * 64 + mi * 16 + grp;
            const int col = colBase + wn * 64 + ni * 8 + t4 * 2;
            float2 v0 = {acc[mi][ni][0], acc[mi][ni][1]};
            float2 v1 = {acc[mi][ni][2], acc[mi][ni][3]};
            if (relu) {
                const float b0 = bias[col], b1 = bias[col + 1];
                v0.x = fmaxf(v0.x + b0, 0.f); v0.y = fmaxf(v0.y + b1, 0.f);
                v1.x = fmaxf(v1.x + b0, 0.f); v1.y = fmaxf(v1.y + b1, 0.f);
            }
            *(float2*)(outp + (size_t)row * DD + col) = v0;
            *(float2*)(outp + (size_t)(row + 8) * DD + col) = v1;
        }
    }
}

// Projection GEMMs: z in [0,6) selects weight slab; out = g_A/g_B slab.
__global__ __launch_bounds__(256, 1)
void k_gemm_proj(const float* __restrict__ Wp, float* gA, float* gB)
{
    extern __shared__ char smem[];
    const int z = blockIdx.z;
    float* outp = ((z & 1) ? gB : gA) + (size_t)(z >> 1) * NN * DD;
    gemm_body(smem, threadIdx.x, g_nf, g_nf, Wp + (size_t)z * DD * DD, DD, DD,
              blockIdx.y * BM, blockIdx.x * BN, outp, nullptr, false);
}

// Node apply: A = [g_nf | g_z] (K=2048), W per node type, bias+relu epilogue.
__global__ __launch_bounds__(256, 1)
void k_gemm_node(const float* __restrict__ Wn,
                 const float* __restrict__ bhn, const float* __restrict__ bon,
                 float* out)
{
    extern __shared__ char smem[];
    const int rowBase = blockIdx.y * BM;
    const float* W    = (rowBase < NH) ? Wn  : Wn + (size_t)2 * DD * DD;
    const float* bias = (rowBase < NH) ? bhn : bon;
    gemm_body(smem, threadIdx.x, g_nf, g_z, W, 2 * DD, 2 * DD,
              rowBase, blockIdx.x * BN, out, bias, true);
}

// ---------------------------------------------------------------------------
__global__ __launch_bounds__(256)
void k_edge_logit(const int* __restrict__ src, const int* __restrict__ dst,
                  const float* __restrict__ b_hh, const float* __restrict__ b_oo,
                  const float* __restrict__ b_ho,
                  const float* __restrict__ W_a, const float* __restrict__ b_a)
{
    const int e = blockIdx.x;
    const int t = (e < EHH) ? 0 : (e < EHH + EOO ? 1 : 2);
    const float* bias = (t == 0) ? b_hh : (t == 1 ? b_oo : b_ho);
    const int s = src[e], d = dst[e];
    const float4* Ar = (const float4*)(g_A + ((size_t)t * NN + s) * DD);
    const float4* Br = (const float4*)(g_B + ((size_t)t * NN + d) * DD);
    const float4* Bi = (const float4*)bias;
    const float4* Wa = (const float4*)W_a;

    const int i = threadIdx.x;
    float4 a = Ar[i], b = Br[i], c = Bi[i], w = Wa[i];
    float acc = fmaxf(a.x + b.x + c.x, 0.f) * w.x
              + fmaxf(a.y + b.y + c.y, 0.f) * w.y
              + fmaxf(a.z + b.z + c.z, 0.f) * w.z
              + fmaxf(a.w + b.w + c.w, 0.f) * w.w;
#pragma unroll
    for (int o = 16; o; o >>= 1) acc += __shfl_down_sync(0xffffffffu, acc, o);
    __shared__ float red[8];
    if ((threadIdx.x & 31) == 0) red[threadIdx.x >> 5] = acc;
    __syncthreads();
    if (threadIdx.x == 0) {
        float s2 = 0.f;
#pragma unroll
        for (int w8 = 0; w8 < 8; w8++) s2 += red[w8];
        float ex = expf(s2 + b_a[0]);
        g_ex[e] = ex;
        atomicAdd(&g_den[d], ex);
    }
}

__global__ __launch_bounds__(256)
void k_scatter(const int* __restrict__ src, const int* __restrict__ dst,
               const float* __restrict__ nf)
{
    const int e = blockIdx.x;
    const int s = src[e], d = dst[e];
    const float alpha = g_ex[e] / g_den[d];
    const float* nr = nf + (size_t)s * DD;
    float* zr = g_z + (size_t)d * DD;
#pragma unroll
    for (int i = threadIdx.x; i < DD; i += 256)
        atomicAdd(&zr[i], alpha * nr[i]);
}

// ---------------------------------------------------------------------------
extern "C" void kernel_launch(void* const* d_in, const int* in_sizes, int n_in,
                              void* d_out, int out_size)
{
    const float* n_f  = (const float*)d_in[0];
    const float* W_hh = (const float*)d_in[1];
    const float* b_hh = (const float*)d_in[2];
    const float* W_oo = (const float*)d_in[3];
    const float* b_oo = (const float*)d_in[4];
    const float* W_ho = (const float*)d_in[5];
    const float* b_ho = (const float*)d_in[6];
    const float* W_a  = (const float*)d_in[7];
    const float* b_a  = (const float*)d_in[8];
    const float* W_hn = (const float*)d_in[9];
    const float* b_hn = (const float*)d_in[10];
    const float* W_on = (const float*)d_in[11];
    const float* b_on = (const float*)d_in[12];
    const int*   esrc = (const int*)d_in[13];
    const int*   edst = (const int*)d_in[14];
    float* out = (float*)d_out;

    float *gA, *gB, *gWp, *gWn;
    cudaGetSymbolAddress((void**)&gA, g_A);
    cudaGetSymbolAddress((void**)&gB, g_B);
    cudaGetSymbolAddress((void**)&gWp, g_Wp);
    cudaGetSymbolAddress((void**)&gWn, g_Wn);

    cudaFuncSetAttribute(k_gemm_proj, cudaFuncAttributeMaxDynamicSharedMemorySize, DYN_SMEM);
    cudaFuncSetAttribute(k_gemm_node, cudaFuncAttributeMaxDynamicSharedMemorySize, DYN_SMEM);

    k_zero<<<(NN * DD) / 256, 256>>>();
    k_cvt_nf<<<(NN * DD / 4) / 256, 256>>>(n_f);

    // Weight transposes (+ tf32 rounding) into [N, K] scratch
    const float* Ws[3] = {W_hh, W_oo, W_ho};
    dim3 tb(32, 8);
    for (int t = 0; t < 3; t++)
        for (int h = 0; h < 2; h++)
            k_transpose<<<dim3(32, 32), tb>>>(Ws[t] + (size_t)h * DD * DD,
                                              gWp + (size_t)(t * 2 + h) * DD * DD, DD, DD);
    k_transpose<<<dim3(64, 32), tb>>>(W_hn, gWn, 2 * DD, DD);
    k_transpose<<<dim3(64, 32), tb>>>(W_on, gWn + (size_t)2 * DD * DD, 2 * DD, DD);

    // 6 projection GEMMs in one launch (z-dim selects weight)
    k_gemm_proj<<<dim3(DD / BN, NN / BM, 6), 256, DYN_SMEM>>>(gWp, gA, gB);

    k_edge_logit<<<EE, 256>>>(esrc, edst, b_hh, b_oo, b_ho, W_a, b_a);
    k_scatter<<<EE, 256>>>(esrc, edst, n_f);
    k_round_z<<<(NN * DD / 4) / 256, 256>>>();

    k_gemm_node<<<dim3(DD / BN, NN / BM), 256, DYN_SMEM>>>(gWn, b_hn, b_on, out);
}

// round 10
// speedup vs baseline: 1.1594x; 1.1594x over previous
#include <cuda_runtime.h>
#include <cuda_fp16.h>
#include <cstdint>

#define NH   4096
#define NN   16384
#define DD   1024
#define EHH  8192
#define EOO  40960
#define EE   65536

// ---------------- GEMM tile config (fp16 mma.sync m16n8k16) ----------------
#define BM      128
#define BN      128
#define BK      32                            // halfs per k-chunk (64 B rows)
#define STAGES  4
#define LDPH    (BK + 8)                      // padded row stride in halfs (80 B)
#define STAGE_BYTES ((BM + BN) * LDPH * 2)    // 20480
#define DYN_SMEM (STAGES * STAGE_BYTES)       // 81920

// ---------------- scratch (__device__ globals; no allocs allowed) ----------
__device__ float  g_A[(size_t)3 * NN * DD];      // A_t = n_f @ W_t[:D]  (fp32)
__device__ float  g_B[(size_t)3 * NN * DD];      // B_t = n_f @ W_t[D:]  (fp32)
__device__ float  g_z[(size_t)NN * DD];          // z_f accumulator (fp32)
__device__ __half g_nfh[(size_t)NN * DD];        // fp16 copy of n_f
__device__ __half g_zh[(size_t)NN * DD];         // fp16 copy of z_f
__device__ float  g_ex[EE];                      // exp(logit)
__device__ float  g_den[NN];                     // softmax denominators
__device__ __half g_Wp[(size_t)6 * DD * DD];     // 6 proj weights, [N,K], fp16
__device__ __half g_Wn[(size_t)2 * DD * 2 * DD]; // 2 node weights, [N,2K], fp16

// ---------------- helpers ---------------------------------------------------
__device__ __forceinline__ uint32_t smem_u32(const void* p) {
    uint32_t a;
    asm("{ .reg .u64 t; cvta.to.shared.u64 t, %1; cvt.u32.u64 %0, t; }"
        : "=r"(a) : "l"(p));
    return a;
}
__device__ __forceinline__ void cp_async16(uint32_t dst, const void* src) {
    asm volatile("cp.async.cg.shared.global [%0], [%1], 16;"
                 :: "r"(dst), "l"(src) : "memory");
}
#define CP_COMMIT()  asm volatile("cp.async.commit_group;" ::: "memory")
#define CP_WAIT2()   asm volatile("cp.async.wait_group 2;" ::: "memory")

__device__ __forceinline__ void mma16(float* c, const uint32_t* a, const uint32_t* b) {
    asm volatile(
        "mma.sync.aligned.m16n8k16.row.col.f32.f16.f16.f32 "
        "{%0,%1,%2,%3}, {%4,%5,%6,%7}, {%8,%9}, {%0,%1,%2,%3};"
        : "+f"(c[0]), "+f"(c[1]), "+f"(c[2]), "+f"(c[3])
        : "r"(a[0]), "r"(a[1]), "r"(a[2]), "r"(a[3]), "r"(b[0]), "r"(b[1]));
}

// ---------------------------------------------------------------------------
__global__ void k_zero() {
    size_t i = (size_t)blockIdx.x * blockDim.x + threadIdx.x;
    g_z[i] = 0.f;
    if (i < NN) g_den[i] = 0.f;
}

// convert n_f -> g_nfh (fp16), 4 elems per thread
__global__ void k_cvt_nf(const float* __restrict__ src) {
    size_t i = (size_t)blockIdx.x * blockDim.x + threadIdx.x;
    float4 v = ((const float4*)src)[i];
    __half2 h0 = __floats2half2_rn(v.x, v.y);
    __half2 h1 = __floats2half2_rn(v.z, v.w);
    ((__half2*)g_nfh)[i * 2] = h0;
    ((__half2*)g_nfh)[i * 2 + 1] = h1;
}
// convert g_z -> g_zh after scatter
__global__ void k_cvt_z() {
    size_t i = (size_t)blockIdx.x * blockDim.x + threadIdx.x;
    float4 v = ((const float4*)g_z)[i];
    ((__half2*)g_zh)[i * 2] = __floats2half2_rn(v.x, v.y);
    ((__half2*)g_zh)[i * 2 + 1] = __floats2half2_rn(v.z, v.w);
}

// transpose + fp16 convert: dst[n*K + k] = half(src[k*Nn + n])
__global__ void k_transpose(const float* __restrict__ src, __half* __restrict__ dst,
                            int K, int Nn) {
    __shared__ float t[32][33];
    const int k0 = blockIdx.x * 32, n0 = blockIdx.y * 32;
    const int x = threadIdx.x, y = threadIdx.y;
#pragma unroll
    for (int i = y; i < 32; i += 8)
        t[i][x] = src[(size_t)(k0 + i) * Nn + n0 + x];
    __syncthreads();
#pragma unroll
    for (int i = y; i < 32; i += 8)
        dst[(size_t)(n0 + i) * K + k0 + x] = __float2half_rn(t[x][i]);
}

// ---------------------------------------------------------------------------
// fp16 mma.sync GEMM: C[BMxBN] = A[rowBase:, :K] @ W^T[colBase:, :K], fp32 out.
// A0 for k<DD, A1 for k>=DD (both ld=DD halfs). W is [N,K] row-major, ld=ldB.
// 8 warps in 4(M) x 2(N); each warp computes 32x64.
__device__ __forceinline__ void gemm_body(
    char* smem, int tid,
    const __half* A0, const __half* A1, const __half* W, int ldB, int K,
    int rowBase, int colBase, float* outp, const float* bias, bool relu)
{
    const int lane = tid & 31, wid = tid >> 5;
    const int grp = lane >> 2, t4 = lane & 3;
    const int wm = wid >> 1, wn = wid & 1;

    const uint32_t sb = smem_u32(smem);
    const int r = tid & 127;            // row within A (tid<128) or B block
    const bool isB = tid >= 128;
    const int KT = K / BK;

    auto prefetch = [&](int st, int kt) {
        const int k0 = kt * BK;
        const uint32_t dbase = sb + st * STAGE_BYTES
                             + (uint32_t)((isB ? BM + r : r) * LDPH) * 2;
        const __half* gsrc;
        if (isB) {
            gsrc = W + (size_t)(colBase + r) * ldB + k0;
        } else {
            const __half* Asrc = (k0 < DD) ? A0 : A1;
            const int kk = (k0 < DD) ? k0 : k0 - DD;
            gsrc = Asrc + (size_t)(rowBase + r) * DD + kk;
        }
#pragma unroll
        for (int i = 0; i < 4; i++)
            cp_async16(dbase + i * 16, gsrc + i * 8);
        CP_COMMIT();
    };

    prefetch(0, 0);
    prefetch(1, 1);
    prefetch(2, 2);

    float acc[2][8][4] = {};

    for (int kt = 0; kt < KT; kt++) {
        CP_WAIT2();
        __syncthreads();
        if (kt + 3 < KT) prefetch((kt + 3) % STAGES, kt + 3);
        else CP_COMMIT();                       // keep group count consistent

        const int st = kt % STAGES;
        const __half* As = (const __half*)(smem + st * STAGE_BYTES);
        const __half* Bs = As + BM * LDPH;

#pragma unroll
        for (int ks = 0; ks < 2; ks++) {
            const int kb = ks * 16;
            uint32_t a[2][4], b[8][2];
#pragma unroll
            for (int mi = 0; mi < 2; mi++) {
                const int r0 = wm * 32 + mi * 16 + grp;
                a[mi][0] = *(const uint32_t*)&As[(r0    ) * LDPH + kb + 2 * t4    ];
                a[mi][1] = *(const uint32_t*)&As[(r0 + 8) * LDPH + kb + 2 * t4    ];
                a[mi][2] = *(const uint32_t*)&As[(r0    ) * LDPH + kb + 2 * t4 + 8];
                a[mi][3] = *(const uint32_t*)&As[(r0 + 8) * LDPH + kb + 2 * t4 + 8];
            }
#pragma unroll
            for (int ni = 0; ni < 8; ni++) {
                const int c0 = wn * 64 + ni * 8 + grp;
                b[ni][0] = *(const uint32_t*)&Bs[c0 * LDPH + kb + 2 * t4    ];
                b[ni][1] = *(const uint32_t*)&Bs[c0 * LDPH + kb + 2 * t4 + 8];
            }
#pragma unroll
            for (int mi = 0; mi < 2; mi++)
#pragma unroll
                for (int ni = 0; ni < 8; ni++)
                    mma16(acc[mi][ni], a[mi], b[ni]);
        }
    }

    // epilogue (c layout identical to m16n8k8)
#pragma unroll
    for (int mi = 0; mi < 2; mi++) {
#pragma unroll
        for (int ni = 0; ni < 8; ni++) {
            const int row = rowBase + wm * 32 + mi * 16 + grp;
            const int col = colBase + wn * 64 + ni * 8 + t4 * 2;
            float2 v0 = {acc[mi][ni][0], acc[mi][ni][1]};
            float2 v1 = {acc[mi][ni][2], acc[mi][ni][3]};
            if (relu) {
                const float b0 = bias[col], b1 = bias[col + 1];
                v0.x = fmaxf(v0.x + b0, 0.f); v0.y = fmaxf(v0.y + b1, 0.f);
                v1.x = fmaxf(v1.x + b0, 0.f); v1.y = fmaxf(v1.y + b1, 0.f);
            }
            *(float2*)(outp + (size_t)row * DD + col) = v0;
            *(float2*)(outp + (size_t)(row + 8) * DD + col) = v1;
        }
    }
}

// Projection GEMMs: z in [0,6) selects weight slab; out = g_A/g_B slab.
__global__ __launch_bounds__(256, 2)
void k_gemm_proj(const __half* __restrict__ Wp, float* gA, float* gB)
{
    extern __shared__ char smem[];
    const int z = blockIdx.z;
    float* outp = ((z & 1) ? gB : gA) + (size_t)(z >> 1) * NN * DD;
    gemm_body(smem, threadIdx.x, g_nfh, g_nfh, Wp + (size_t)z * DD * DD, DD, DD,
              blockIdx.y * BM, blockIdx.x * BN, outp, nullptr, false);
}

// Node apply: A = [g_nfh | g_zh] (K=2048), W per node type, bias+relu.
__global__ __launch_bounds__(256, 2)
void k_gemm_node(const __half* __restrict__ Wn,
                 const float* __restrict__ bhn, const float* __restrict__ bon,
                 float* out)
{
    extern __shared__ char smem[];
    const int rowBase = blockIdx.y * BM;
    const __half* W   = (rowBase < NH) ? Wn  : Wn + (size_t)2 * DD * DD;
    const float* bias = (rowBase < NH) ? bhn : bon;
    gemm_body(smem, threadIdx.x, g_nfh, g_zh, W, 2 * DD, 2 * DD,
              rowBase, blockIdx.x * BN, out, bias, true);
}

// ---------------------------------------------------------------------------
__global__ __launch_bounds__(256)
void k_edge_logit(const int* __restrict__ src, const int* __restrict__ dst,
                  const float* __restrict__ b_hh, const float* __restrict__ b_oo,
                  const float* __restrict__ b_ho,
                  const float* __restrict__ W_a, const float* __restrict__ b_a)
{
    const int e = blockIdx.x;
    const int t = (e < EHH) ? 0 : (e < EHH + EOO ? 1 : 2);
    const float* bias = (t == 0) ? b_hh : (t == 1 ? b_oo : b_ho);
    const int s = src[e], d = dst[e];
    const float4* Ar = (const float4*)(g_A + ((size_t)t * NN + s) * DD);
    const float4* Br = (const float4*)(g_B + ((size_t)t * NN + d) * DD);
    const float4* Bi = (const float4*)bias;
    const float4* Wa = (const float4*)W_a;

    const int i = threadIdx.x;
    float4 a = Ar[i], b = Br[i], c = Bi[i], w = Wa[i];
    float acc = fmaxf(a.x + b.x + c.x, 0.f) * w.x
              + fmaxf(a.y + b.y + c.y, 0.f) * w.y
              + fmaxf(a.z + b.z + c.z, 0.f) * w.z
              + fmaxf(a.w + b.w + c.w, 0.f) * w.w;
#pragma unroll
    for (int o = 16; o; o >>= 1) acc += __shfl_down_sync(0xffffffffu, acc, o);
    __shared__ float red[8];
    if ((threadIdx.x & 31) == 0) red[threadIdx.x >> 5] = acc;
    __syncthreads();
    if (threadIdx.x == 0) {
        float s2 = 0.f;
#pragma unroll
        for (int w8 = 0; w8 < 8; w8++) s2 += red[w8];
        float ex = expf(s2 + b_a[0]);
        g_ex[e] = ex;
        atomicAdd(&g_den[d], ex);
    }
}

__global__ __launch_bounds__(256)
void k_scatter(const int* __restrict__ src, const int* __restrict__ dst,
               const float* __restrict__ nf)
{
    const int e = blockIdx.x;
    const int s = src[e], d = dst[e];
    const float alpha = g_ex[e] / g_den[d];
    const float* nr = nf + (size_t)s * DD;
    float* zr = g_z + (size_t)d * DD;
#pragma unroll
    for (int i = threadIdx.x; i < DD; i += 256)
        atomicAdd(&zr[i], alpha * nr[i]);
}

// ---------------------------------------------------------------------------
extern "C" void kernel_launch(void* const* d_in, const int* in_sizes, int n_in,
                              void* d_out, int out_size)
{
    const float* n_f  = (const float*)d_in[0];
    const float* W_hh = (const float*)d_in[1];
    const float* b_hh = (const float*)d_in[2];
    const float* W_oo = (const float*)d_in[3];
    const float* b_oo = (const float*)d_in[4];
    const float* W_ho = (const float*)d_in[5];
    const float* b_ho = (const float*)d_in[6];
    const float* W_a  = (const float*)d_in[7];
    const float* b_a  = (const float*)d_in[8];
    const float* W_hn = (const float*)d_in[9];
    const float* b_hn = (const float*)d_in[10];
    const float* W_on = (const float*)d_in[11];
    const float* b_on = (const float*)d_in[12];
    const int*   esrc = (const int*)d_in[13];
    const int*   edst = (const int*)d_in[14];
    float* out = (float*)d_out;

    float *gA, *gB;
    __half *gWp, *gWn;
    cudaGetSymbolAddress((void**)&gA, g_A);
    cudaGetSymbolAddress((void**)&gB, g_B);
    cudaGetSymbolAddress((void**)&gWp, g_Wp);
    cudaGetSymbolAddress((void**)&gWn, g_Wn);

    cudaFuncSetAttribute(k_gemm_proj, cudaFuncAttributeMaxDynamicSharedMemorySize, DYN_SMEM);
    cudaFuncSetAttribute(k_gemm_node, cudaFuncAttributeMaxDynamicSharedMemorySize, DYN_SMEM);

    k_zero<<<(NN * DD) / 256, 256>>>();
    k_cvt_nf<<<(NN * DD / 4) / 256, 256>>>(n_f);

    // Weight transposes (+ fp16 convert) into [N, K] scratch
    const float* Ws[3] = {W_hh, W_oo, W_ho};
    dim3 tb(32, 8);
    for (int t = 0; t < 3; t++)
        for (int h = 0; h < 2; h++)
            k_transpose<<<dim3(32, 32), tb>>>(Ws[t] + (size_t)h * DD * DD,
                                              gWp + (size_t)(t * 2 + h) * DD * DD, DD, DD);
    k_transpose<<<dim3(64, 32), tb>>>(W_hn, gWn, 2 * DD, DD);
    k_transpose<<<dim3(64, 32), tb>>>(W_on, gWn + (size_t)2 * DD * DD, 2 * DD, DD);

    // 6 projection GEMMs in one launch (z-dim selects weight)
    k_gemm_proj<<<dim3(DD / BN, NN / BM, 6), 256, DYN_SMEM>>>(gWp, gA, gB);

    k_edge_logit<<<EE, 256>>>(esrc, edst, b_hh, b_oo, b_ho, W_a, b_a);
    k_scatter<<<EE, 256>>>(esrc, edst, n_f);
    k_cvt_z<<<(NN * DD / 4) / 256, 256>>>();

    k_gemm_node<<<dim3(DD / BN, NN / BM), 256, DYN_SMEM>>>(gWn, b_hn, b_on, out);
}

// round 14
// speedup vs baseline: 1.1908x; 1.0270x over previous
#include <cuda_runtime.h>
#include <cuda_fp16.h>
#include <cstdint>

#define NH   4096
#define NN   16384
#define DD   1024
#define EHH  8192
#define EOO  40960
#define EE   65536

// ---------------- GEMM tile config (fp16 mma.sync m16n8k16) ----------------
#define BM      128
#define BN      128
#define BK      32                            // halfs per k-chunk (64 B rows)
#define STAGES  4
#define LDPH    (BK + 8)                      // padded row stride in halfs (80 B)
#define STAGE_BYTES ((BM + BN) * LDPH * 2)    // 20480
#define DYN_SMEM (STAGES * STAGE_BYTES)       // 81920

// ---------------- scratch (__device__ globals; no allocs allowed) ----------
__device__ __half g_Ah[(size_t)3 * NN * DD];     // A_t = n_f @ W_t[:D]  (fp16)
__device__ __half g_Bh[(size_t)3 * NN * DD];     // B_t = n_f @ W_t[D:]  (fp16)
__device__ __half g_nfh[(size_t)NN * DD];        // fp16 copy of n_f
__device__ __half g_zh[(size_t)NN * DD];         // fp16 z_f
__device__ float  g_ex[EE];                      // exp(logit)
__device__ float  g_den[NN];                     // softmax denominators
__device__ __half g_Wp[(size_t)6 * DD * DD];     // 6 proj weights, [N,K], fp16
__device__ __half g_Wn[(size_t)2 * DD * 2 * DD]; // 2 node weights, [N,2K], fp16
__device__ int    g_off[NN + 1];                 // CSR offsets (by dst)
__device__ int    g_cnt[NN];                     // fill cursors
__device__ int    g_eid[EE];                     // CSR edge ids

// ---------------- helpers ---------------------------------------------------
__device__ __forceinline__ uint32_t smem_u32(const void* p) {
    uint32_t a;
    asm("{ .reg .u64 t; cvta.to.shared.u64 t, %1; cvt.u32.u64 %0, t; }"
        : "=r"(a) : "l"(p));
    return a;
}
__device__ __forceinline__ void cp_async16(uint32_t dst, const void* src) {
    asm volatile("cp.async.cg.shared.global [%0], [%1], 16;"
                 :: "r"(dst), "l"(src) : "memory");
}
#define CP_COMMIT()  asm volatile("cp.async.commit_group;" ::: "memory")
#define CP_WAIT2()   asm volatile("cp.async.wait_group 2;" ::: "memory")

__device__ __forceinline__ void mma16(float* c, const uint32_t* a, const uint32_t* b) {
    asm volatile(
        "mma.sync.aligned.m16n8k16.row.col.f32.f16.f16.f32 "
        "{%0,%1,%2,%3}, {%4,%5,%6,%7}, {%8,%9}, {%0,%1,%2,%3};"
        : "+f"(c[0]), "+f"(c[1]), "+f"(c[2]), "+f"(c[3])
        : "r"(a[0]), "r"(a[1]), "r"(a[2]), "r"(a[3]), "r"(b[0]), "r"(b[1]));
}

// ---------------------------------------------------------------------------
__global__ void k_zero() {
    int i = blockIdx.x * blockDim.x + threadIdx.x;
    if (i < NN) { g_den[i] = 0.f; g_cnt[i] = 0; }
    if (i <= NN) g_off[i] = 0;
}

// convert n_f -> g_nfh (fp16), 4 elems per thread
__global__ void k_cvt_nf(const float* __restrict__ src) {
    size_t i = (size_t)blockIdx.x * blockDim.x + threadIdx.x;
    float4 v = ((const float4*)src)[i];
    ((__half2*)g_nfh)[i * 2]     = __floats2half2_rn(v.x, v.y);
    ((__half2*)g_nfh)[i * 2 + 1] = __floats2half2_rn(v.z, v.w);
}

// batched transpose + fp16 convert: dst[n*K + k] = half(src[k*Nn + n])
struct Ptr6 { const float* p[6]; };
__global__ void k_transpose6(const Ptr6 srcs, __half* __restrict__ dst0,
                             int K, int Nn, size_t slab) {
    __shared__ float t[32][33];
    const float* src = srcs.p[blockIdx.z];
    __half* dst = dst0 + slab * blockIdx.z;
    const int k0 = blockIdx.x * 32, n0 = blockIdx.y * 32;
    const int x = threadIdx.x, y = threadIdx.y;
#pragma unroll
    for (int i = y; i < 32; i += 8)
        t[i][x] = src[(size_t)(k0 + i) * Nn + n0 + x];
    __syncthreads();
#pragma unroll
    for (int i = y; i < 32; i += 8)
        dst[(size_t)(n0 + i) * K + k0 + x] = __float2half_rn(t[x][i]);
}

// ---------------- CSR build ------------------------------------------------
__global__ void k_count(const int* __restrict__ dst) {
    int e = blockIdx.x * blockDim.x + threadIdx.x;
    atomicAdd(&g_off[dst[e] + 1], 1);
}
// single-block inclusive scan of g_off[1..NN] (NN = 1024*16)
__global__ __launch_bounds__(1024) void k_scan() {
    __shared__ int part[1024];
    const int tid = threadIdx.x;
    int v[16], s = 0;
#pragma unroll
    for (int i = 0; i < 16; i++) { v[i] = g_off[1 + tid * 16 + i]; s += v[i]; }
    part[tid] = s;
    __syncthreads();
    for (int off = 1; off < 1024; off <<= 1) {
        int t = (tid >= off) ? part[tid - off] : 0;
        __syncthreads();
        part[tid] += t;
        __syncthreads();
    }
    int run = (tid == 0) ? 0 : part[tid - 1];
#pragma unroll
    for (int i = 0; i < 16; i++) { run += v[i]; g_off[1 + tid * 16 + i] = run; }
}
__global__ void k_fill(const int* __restrict__ dst) {
    int e = blockIdx.x * blockDim.x + threadIdx.x;
    int d = dst[e];
    int pos = g_off[d] + atomicAdd(&g_cnt[d], 1);
    g_eid[pos] = e;
}

// ---------------------------------------------------------------------------
// fp16 mma.sync GEMM. 8 warps in 4(M) x 2(N); warp tile 32x64.
// Epilogue: HALF_OUT -> fp16 store (no bias); else fp32 bias+relu store.
template <bool HALF_OUT>
__device__ __forceinline__ void gemm_body(
    char* smem, int tid,
    const __half* A0, const __half* A1, const __half* W, int ldB, int K,
    int rowBase, int colBase, float* outf, __half* outh,
    const float* bias)
{
    const int lane = tid & 31, wid = tid >> 5;
    const int grp = lane >> 2, t4 = lane & 3;
    const int wm = wid >> 1, wn = wid & 1;

    const uint32_t sb = smem_u32(smem);
    const int r = tid & 127;
    const bool isB = tid >= 128;
    const int KT = K / BK;

    auto prefetch = [&](int st, int kt) {
        const int k0 = kt * BK;
        const uint32_t dbase = sb + st * STAGE_BYTES
                             + (uint32_t)((isB ? BM + r : r) * LDPH) * 2;
        const __half* gsrc;
        if (isB) {
            gsrc = W + (size_t)(colBase + r) * ldB + k0;
        } else {
            const __half* Asrc = (k0 < DD) ? A0 : A1;
            const int kk = (k0 < DD) ? k0 : k0 - DD;
            gsrc = Asrc + (size_t)(rowBase + r) * DD + kk;
        }
#pragma unroll
        for (int i = 0; i < 4; i++)
            cp_async16(dbase + i * 16, gsrc + i * 8);
        CP_COMMIT();
    };

    prefetch(0, 0);
    prefetch(1, 1);
    prefetch(2, 2);

    float acc[2][8][4] = {};

    for (int kt = 0; kt < KT; kt++) {
        CP_WAIT2();
        __syncthreads();
        if (kt + 3 < KT) prefetch((kt + 3) % STAGES, kt + 3);
        else CP_COMMIT();

        const int st = kt % STAGES;
        const __half* As = (const __half*)(smem + st * STAGE_BYTES);
        const __half* Bs = As + BM * LDPH;

#pragma unroll
        for (int ks = 0; ks < 2; ks++) {
            const int kb = ks * 16;
            uint32_t a[2][4], b[8][2];
#pragma unroll
            for (int mi = 0; mi < 2; mi++) {
                const int r0 = wm * 32 + mi * 16 + grp;
                a[mi][0] = *(const uint32_t*)&As[(r0    ) * LDPH + kb + 2 * t4    ];
                a[mi][1] = *(const uint32_t*)&As[(r0 + 8) * LDPH + kb + 2 * t4    ];
                a[mi][2] = *(const uint32_t*)&As[(r0    ) * LDPH + kb + 2 * t4 + 8];
                a[mi][3] = *(const uint32_t*)&As[(r0 + 8) * LDPH + kb + 2 * t4 + 8];
            }
#pragma unroll
            for (int ni = 0; ni < 8; ni++) {
                const int c0 = wn * 64 + ni * 8 + grp;
                b[ni][0] = *(const uint32_t*)&Bs[c0 * LDPH + kb + 2 * t4    ];
                b[ni][1] = *(const uint32_t*)&Bs[c0 * LDPH + kb + 2 * t4 + 8];
            }
#pragma unroll
            for (int mi = 0; mi < 2; mi++)
#pragma unroll
                for (int ni = 0; ni < 8; ni++)
                    mma16(acc[mi][ni], a[mi], b[ni]);
        }
    }

#pragma unroll
    for (int mi = 0; mi < 2; mi++) {
#pragma unroll
        for (int ni = 0; ni < 8; ni++) {
            const int row = rowBase + wm * 32 + mi * 16 + grp;
            const int col = colBase + wn * 64 + ni * 8 + t4 * 2;
            if (HALF_OUT) {
                *(__half2*)(outh + (size_t)row * DD + col) =
                    __floats2half2_rn(acc[mi][ni][0], acc[mi][ni][1]);
                *(__half2*)(outh + (size_t)(row + 8) * DD + col) =
                    __floats2half2_rn(acc[mi][ni][2], acc[mi][ni][3]);
            } else {
                const float b0 = bias[col], b1 = bias[col + 1];
                float2 v0 = {fmaxf(acc[mi][ni][0] + b0, 0.f),
                             fmaxf(acc[mi][ni][1] + b1, 0.f)};
                float2 v1 = {fmaxf(acc[mi][ni][2] + b0, 0.f),
                             fmaxf(acc[mi][ni][3] + b1, 0.f)};
                *(float2*)(outf + (size_t)row * DD + col) = v0;
                *(float2*)(outf + (size_t)(row + 8) * DD + col) = v1;
            }
        }
    }
}

// Projection GEMMs: z in [0,6) selects weight slab; fp16 out to g_Ah/g_Bh.
__global__ __launch_bounds__(256, 2)
void k_gemm_proj(const __half* __restrict__ Wp)
{
    extern __shared__ char smem[];
    const int z = blockIdx.z;
    __half* outp = ((z & 1) ? g_Bh : g_Ah) + (size_t)(z >> 1) * NN * DD;
    gemm_body<true>(smem, threadIdx.x, g_nfh, g_nfh, Wp + (size_t)z * DD * DD,
                    DD, DD, blockIdx.y * BM, blockIdx.x * BN,
                    nullptr, outp, nullptr);
}

// Node apply: A = [g_nfh | g_zh] (K=2048), W per node type, bias+relu, fp32 out.
__global__ __launch_bounds__(256, 2)
void k_gemm_node(const __half* __restrict__ Wn,
                 const float* __restrict__ bhn, const float* __restrict__ bon,
                 float* out)
{
    extern __shared__ char smem[];
    const int rowBase = blockIdx.y * BM;
    const __half* W   = (rowBase < NH) ? Wn  : Wn + (size_t)2 * DD * DD;
    const float* bias = (rowBase < NH) ? bhn : bon;
    gemm_body<false>(smem, threadIdx.x, g_nfh, g_zh, W, 2 * DD, 2 * DD,
                     rowBase, blockIdx.x * BN, out, nullptr, bias);
}

// ---------------------------------------------------------------------------
// warp-per-edge logits; fp16 A/B reads, fp32 math
__global__ __launch_bounds__(256)
void k_edge_logit(const int* __restrict__ src, const int* __restrict__ dst,
                  const float* __restrict__ b_hh, const float* __restrict__ b_oo,
                  const float* __restrict__ b_ho,
                  const float* __restrict__ W_a, const float* __restrict__ b_a)
{
    const int warp = threadIdx.x >> 5, lane = threadIdx.x & 31;
    const int e = blockIdx.x * 8 + warp;
    const int t = (e < EHH) ? 0 : (e < EHH + EOO ? 1 : 2);
    const float* bias = (t == 0) ? b_hh : (t == 1 ? b_oo : b_ho);
    const int s = src[e], d = dst[e];
    const uint4* Ar = (const uint4*)(g_Ah + ((size_t)t * NN + s) * DD);
    const uint4* Br = (const uint4*)(g_Bh + ((size_t)t * NN + d) * DD);

    float acc = 0.f;
#pragma unroll
    for (int i = 0; i < 4; i++) {
        const int idx = i * 32 + lane;     // uint4 index (8 halfs each)
        uint4 av = Ar[idx], bv = Br[idx];
        const __half2* ah = (const __half2*)&av;
        const __half2* bh = (const __half2*)&bv;
        const int c0 = idx * 8;
#pragma unroll
        for (int j = 0; j < 4; j++) {
            float2 fa = __half22float2(ah[j]);
            float2 fb = __half22float2(bh[j]);
            const int c = c0 + j * 2;
            acc += fmaxf(fa.x + fb.x + bias[c], 0.f) * W_a[c]
                 + fmaxf(fa.y + fb.y + bias[c + 1], 0.f) * W_a[c + 1];
        }
    }
#pragma unroll
    for (int o = 16; o; o >>= 1) acc += __shfl_down_sync(0xffffffffu, acc, o);
    if (lane == 0) {
        float ex = expf(acc + b_a[0]);
        g_ex[e] = ex;
        atomicAdd(&g_den[d], ex);
    }
}

// ---------------------------------------------------------------------------
// CSR gather: block per dst node; z_f[d] = (sum ex_e * n_f[src_e]) / den[d]
__global__ __launch_bounds__(256)
void k_gather(const int* __restrict__ src)
{
    const int d = blockIdx.x;
    const int beg = g_off[d], end = g_off[d + 1];
    const int tid = threadIdx.x;
    __shared__ int   ss[256];
    __shared__ float sa[256];
    float4 acc = {0.f, 0.f, 0.f, 0.f};

    for (int base = beg; base < end; base += 256) {
        const int n = min(256, end - base);
        if (tid < n) {
            const int e = g_eid[base + tid];
            ss[tid] = src[e];
            sa[tid] = g_ex[e];
        }
        __syncthreads();
        for (int j = 0; j < n; j++) {
            const int s = ss[j];
            const float al = sa[j];
            uint2 hv = *(const uint2*)(g_nfh + (size_t)s * DD + tid * 4);
            float2 f0 = __half22float2(*(const __half2*)&hv.x);
            float2 f1 = __half22float2(*(const __half2*)&hv.y);
            acc.x += al * f0.x; acc.y += al * f0.y;
            acc.z += al * f1.x; acc.w += al * f1.y;
        }
        __syncthreads();
    }
    const float inv = (end > beg) ? 1.f / g_den[d] : 0.f;
    uint2 o;
    *(__half2*)&o.x = __floats2half2_rn(acc.x * inv, acc.y * inv);
    *(__half2*)&o.y = __floats2half2_rn(acc.z * inv, acc.w * inv);
    *(uint2*)(g_zh + (size_t)d * DD + tid * 4) = o;
}

// ---------------------------------------------------------------------------
extern "C" void kernel_launch(void* const* d_in, const int* in_sizes, int n_in,
                              void* d_out, int out_size)
{
    const float* n_f  = (const float*)d_in[0];
    const float* W_hh = (const float*)d_in[1];
    const float* b_hh = (const float*)d_in[2];
    const float* W_oo = (const float*)d_in[3];
    const float* b_oo = (const float*)d_in[4];
    const float* W_ho = (const float*)d_in[5];
    const float* b_ho = (const float*)d_in[6];
    const float* W_a  = (const float*)d_in[7];
    const float* b_a  = (const float*)d_in[8];
    const float* W_hn = (const float*)d_in[9];
    const float* b_hn = (const float*)d_in[10];
    const float* W_on = (const float*)d_in[11];
    const float* b_on = (const float*)d_in[12];
    const int*   esrc = (const int*)d_in[13];
    const int*   edst = (const int*)d_in[14];
    float* out = (float*)d_out;

    __half *gWp, *gWn;
    cudaGetSymbolAddress((void**)&gWp, g_Wp);
    cudaGetSymbolAddress((void**)&gWn, g_Wn);

    cudaFuncSetAttribute(k_gemm_proj, cudaFuncAttributeMaxDynamicSharedMemorySize, DYN_SMEM);
    cudaFuncSetAttribute(k_gemm_node, cudaFuncAttributeMaxDynamicSharedMemorySize, DYN_SMEM);

    k_zero<<<(NN + 256) / 256, 256>>>();
    k_cvt_nf<<<(NN * DD / 4) / 256, 256>>>(n_f);

    // Batched weight transposes (+ fp16 convert) into [N, K] scratch
    Ptr6 wp;
    wp.p[0] = W_hh; wp.p[1] = W_hh + (size_t)DD * DD;
    wp.p[2] = W_oo; wp.p[3] = W_oo + (size_t)DD * DD;
    wp.p[4] = W_ho; wp.p[5] = W_ho + (size_t)DD * DD;
    Ptr6 wn;
    wn.p[0] = W_hn; wn.p[1] = W_on;
    dim3 tb(32, 8);
    k_transpose6<<<dim3(32, 32, 6), tb>>>(wp, gWp, DD, DD, (size_t)DD * DD);
    k_transpose6<<<dim3(64, 32, 2), tb>>>(wn, gWn, 2 * DD, DD, (size_t)2 * DD * DD);

    // CSR build (independent of GEMMs)
    k_count<<<EE / 256, 256>>>(edst);
    k_scan<<<1, 1024>>>();
    k_fill<<<EE / 256, 256>>>(edst);

    // 6 projection GEMMs in one launch (z-dim selects weight)
    k_gemm_proj<<<dim3(DD / BN, NN / BM, 6), 256, DYN_SMEM>>>(gWp);

    k_edge_logit<<<EE / 8, 256>>>(esrc, edst, b_hh, b_oo, b_ho, W_a, b_a);
    k_gather<<<NN, 256>>>(esrc);

    k_gemm_node<<<dim3(DD / BN, NN / BM), 256, DYN_SMEM>>>(gWn, b_hn, b_on, out);
}

// round 15
// speedup vs baseline: 1.2474x; 1.0476x over previous
#include <cuda_runtime.h>
#include <cuda_fp16.h>
#include <cstdint>

#define NH   4096
#define NN   16384
#define DD   1024
#define EHH  8192
#define EOO  40960
#define EE   65536

// ---------------- GEMM tile config (fp16 mma.sync m16n8k16 + ldmatrix) -----
#define BM      128
#define BN      128
#define BK      64                            // halfs per k-chunk (128 B rows)
#define STAGES  3
#define LDPH    (BK + 8)                      // padded row stride in halfs (144 B)
#define STAGE_BYTES ((BM + BN) * LDPH * 2)    // 36864
#define DYN_SMEM (STAGES * STAGE_BYTES)       // 110592

// ---------------- scratch (__device__ globals; no allocs allowed) ----------
__device__ __half g_Ah[(size_t)3 * NN * DD];     // A_t = n_f @ W_t[:D]  (fp16)
__device__ __half g_Bh[(size_t)3 * NN * DD];     // B_t = n_f @ W_t[D:]  (fp16)
__device__ __half g_nfh[(size_t)NN * DD];        // fp16 copy of n_f
__device__ __half g_zh[(size_t)NN * DD];         // fp16 z_f
__device__ float  g_ex[EE];                      // exp(logit)
__device__ float  g_den[NN];                     // softmax denominators
__device__ __half g_Wp[(size_t)6 * DD * DD];     // 6 proj weights, [N,K], fp16
__device__ __half g_Wn[(size_t)2 * DD * 2 * DD]; // 2 node weights, [N,2K], fp16
__device__ int    g_off[NN + 1];                 // CSR offsets (by dst)
__device__ int    g_cnt[NN];                     // fill cursors
__device__ int    g_eid[EE];                     // CSR edge ids

// ---------------- helpers ---------------------------------------------------
__device__ __forceinline__ uint32_t smem_u32(const void* p) {
    uint32_t a;
    asm("{ .reg .u64 t; cvta.to.shared.u64 t, %1; cvt.u32.u64 %0, t; }"
        : "=r"(a) : "l"(p));
    return a;
}
__device__ __forceinline__ void cp_async16(uint32_t dst, const void* src) {
    asm volatile("cp.async.cg.shared.global [%0], [%1], 16;"
                 :: "r"(dst), "l"(src) : "memory");
}
#define CP_COMMIT()  asm volatile("cp.async.commit_group;" ::: "memory")
#define CP_WAIT1()   asm volatile("cp.async.wait_group 1;" ::: "memory")

__device__ __forceinline__ void mma16(float* c, const uint32_t* a, const uint32_t* b) {
    asm volatile(
        "mma.sync.aligned.m16n8k16.row.col.f32.f16.f16.f32 "
        "{%0,%1,%2,%3}, {%4,%5,%6,%7}, {%8,%9}, {%0,%1,%2,%3};"
        : "+f"(c[0]), "+f"(c[1]), "+f"(c[2]), "+f"(c[3])
        : "r"(a[0]), "r"(a[1]), "r"(a[2]), "r"(a[3]), "r"(b[0]), "r"(b[1]));
}
__device__ __forceinline__ void ldm_x4(uint32_t* r, uint32_t addr) {
    asm volatile("ldmatrix.sync.aligned.m8n8.x4.shared.b16 {%0,%1,%2,%3}, [%4];"
                 : "=r"(r[0]), "=r"(r[1]), "=r"(r[2]), "=r"(r[3]) : "r"(addr));
}

// ---------------------------------------------------------------------------
__global__ void k_zero() {
    int i = blockIdx.x * blockDim.x + threadIdx.x;
    if (i < NN) { g_den[i] = 0.f; g_cnt[i] = 0; }
    if (i <= NN) g_off[i] = 0;
}

// convert n_f -> g_nfh (fp16), 4 elems per thread
__global__ void k_cvt_nf(const float* __restrict__ src) {
    size_t i = (size_t)blockIdx.x * blockDim.x + threadIdx.x;
    float4 v = ((const float4*)src)[i];
    ((__half2*)g_nfh)[i * 2]     = __floats2half2_rn(v.x, v.y);
    ((__half2*)g_nfh)[i * 2 + 1] = __floats2half2_rn(v.z, v.w);
}

// batched transpose + fp16 convert: dst[n*K + k] = half(src[k*Nn + n])
struct Ptr6 { const float* p[6]; };
__global__ void k_transpose6(const Ptr6 srcs, __half* __restrict__ dst0,
                             int K, int Nn, size_t slab) {
    __shared__ float t[32][33];
    const float* src = srcs.p[blockIdx.z];
    __half* dst = dst0 + slab * blockIdx.z;
    const int k0 = blockIdx.x * 32, n0 = blockIdx.y * 32;
    const int x = threadIdx.x, y = threadIdx.y;
#pragma unroll
    for (int i = y; i < 32; i += 8)
        t[i][x] = src[(size_t)(k0 + i) * Nn + n0 + x];
    __syncthreads();
#pragma unroll
    for (int i = y; i < 32; i += 8)
        dst[(size_t)(n0 + i) * K + k0 + x] = __float2half_rn(t[x][i]);
}

// ---------------- CSR build ------------------------------------------------
__global__ void k_count(const int* __restrict__ dst) {
    int e = blockIdx.x * blockDim.x + threadIdx.x;
    atomicAdd(&g_off[dst[e] + 1], 1);
}
__global__ __launch_bounds__(1024) void k_scan() {
    __shared__ int part[1024];
    const int tid = threadIdx.x;
    int v[16], s = 0;
#pragma unroll
    for (int i = 0; i < 16; i++) { v[i] = g_off[1 + tid * 16 + i]; s += v[i]; }
    part[tid] = s;
    __syncthreads();
    for (int off = 1; off < 1024; off <<= 1) {
        int t = (tid >= off) ? part[tid - off] : 0;
        __syncthreads();
        part[tid] += t;
        __syncthreads();
    }
    int run = (tid == 0) ? 0 : part[tid - 1];
#pragma unroll
    for (int i = 0; i < 16; i++) { run += v[i]; g_off[1 + tid * 16 + i] = run; }
}
__global__ void k_fill(const int* __restrict__ dst) {
    int e = blockIdx.x * blockDim.x + threadIdx.x;
    int d = dst[e];
    int pos = g_off[d] + atomicAdd(&g_cnt[d], 1);
    g_eid[pos] = e;
}

// ---------------------------------------------------------------------------
// fp16 mma.sync GEMM with ldmatrix fragment loads.
// 8 warps in 4(M) x 2(N); warp tile 32x64. BK=64 halfs per stage.
template <bool HALF_OUT>
__device__ __forceinline__ void gemm_body(
    char* smem, int tid,
    const __half* A0, const __half* A1, const __half* W, int ldB, int K,
    int rowBase, int colBase, float* outf, __half* outh,
    const float* bias)
{
    const int lane = tid & 31, wid = tid >> 5;
    const int grp = lane >> 2, t4 = lane & 3;
    const int wm = wid >> 1, wn = wid & 1;

    const uint32_t sb = smem_u32(smem);
    const int r = tid & 127;
    const bool isB = tid >= 128;
    const int KT = K / BK;

    // ldmatrix per-lane byte offsets within a stage
    const int l7 = lane & 7, l8 = (lane >> 3) & 1, l16 = (lane >> 4) & 1;
    uint32_t aOff[2], bOff[4];
#pragma unroll
    for (int mi = 0; mi < 2; mi++)
        aOff[mi] = (uint32_t)((wm * 32 + mi * 16 + l7 + l8 * 8) * LDPH + l16 * 8) * 2;
#pragma unroll
    for (int p = 0; p < 4; p++)
        bOff[p] = (uint32_t)((BM + wn * 64 + p * 16 + l16 * 8 + l7) * LDPH + l8 * 8) * 2;

    auto prefetch = [&](int st, int kt) {
        const int k0 = kt * BK;
        const uint32_t dbase = sb + st * STAGE_BYTES
                             + (uint32_t)((isB ? BM + r : r) * LDPH) * 2;
        const __half* gsrc;
        if (isB) {
            gsrc = W + (size_t)(colBase + r) * ldB + k0;
        } else {
            const __half* Asrc = (k0 < DD) ? A0 : A1;
            const int kk = (k0 < DD) ? k0 : k0 - DD;
            gsrc = Asrc + (size_t)(rowBase + r) * DD + kk;
        }
#pragma unroll
        for (int i = 0; i < 8; i++)
            cp_async16(dbase + i * 16, gsrc + i * 8);
        CP_COMMIT();
    };

    prefetch(0, 0);
    prefetch(1, 1);

    float acc[2][8][4] = {};

    for (int kt = 0; kt < KT; kt++) {
        CP_WAIT1();
        __syncthreads();
        if (kt + 2 < KT) prefetch((kt + 2) % STAGES, kt + 2);
        else CP_COMMIT();

        const uint32_t stBase = sb + (uint32_t)((kt % STAGES) * STAGE_BYTES);

#pragma unroll
        for (int ks = 0; ks < 4; ks++) {
            const uint32_t kbb = ks * 32;          // 16 halfs = 32 bytes
            uint32_t a[2][4], b[4][4];
#pragma unroll
            for (int mi = 0; mi < 2; mi++)
                ldm_x4(a[mi], stBase + aOff[mi] + kbb);
#pragma unroll
            for (int p = 0; p < 4; p++)
                ldm_x4(b[p], stBase + bOff[p] + kbb);
            // b[p] regs: {ni=2p lo, ni=2p hi, ni=2p+1 lo, ni=2p+1 hi}
#pragma unroll
            for (int mi = 0; mi < 2; mi++)
#pragma unroll
                for (int p = 0; p < 4; p++) {
                    mma16(acc[mi][2 * p],     a[mi], &b[p][0]);
                    mma16(acc[mi][2 * p + 1], a[mi], &b[p][2]);
                }
        }
    }

#pragma unroll
    for (int mi = 0; mi < 2; mi++) {
#pragma unroll
        for (int ni = 0; ni < 8; ni++) {
            const int row = rowBase + wm * 32 + mi * 16 + grp;
            const int col = colBase + wn * 64 + ni * 8 + t4 * 2;
            if (HALF_OUT) {
                *(__half2*)(outh + (size_t)row * DD + col) =
                    __floats2half2_rn(acc[mi][ni][0], acc[mi][ni][1]);
                *(__half2*)(outh + (size_t)(row + 8) * DD + col) =
                    __floats2half2_rn(acc[mi][ni][2], acc[mi][ni][3]);
            } else {
                const float b0 = bias[col], b1 = bias[col + 1];
                float2 v0 = {fmaxf(acc[mi][ni][0] + b0, 0.f),
                             fmaxf(acc[mi][ni][1] + b1, 0.f)};
                float2 v1 = {fmaxf(acc[mi][ni][2] + b0, 0.f),
                             fmaxf(acc[mi][ni][3] + b1, 0.f)};
                *(float2*)(outf + (size_t)row * DD + col) = v0;
                *(float2*)(outf + (size_t)(row + 8) * DD + col) = v1;
            }
        }
    }
}

// Projection GEMMs: z in [0,6) selects weight slab; fp16 out to g_Ah/g_Bh.
__global__ __launch_bounds__(256, 2)
void k_gemm_proj(const __half* __restrict__ Wp)
{
    extern __shared__ char smem[];
    const int z = blockIdx.z;
    __half* outp = ((z & 1) ? g_Bh : g_Ah) + (size_t)(z >> 1) * NN * DD;
    gemm_body<true>(smem, threadIdx.x, g_nfh, g_nfh, Wp + (size_t)z * DD * DD,
                    DD, DD, blockIdx.y * BM, blockIdx.x * BN,
                    nullptr, outp, nullptr);
}

// Node apply: A = [g_nfh | g_zh] (K=2048), W per node type, bias+relu, fp32 out.
__global__ __launch_bounds__(256, 2)
void k_gemm_node(const __half* __restrict__ Wn,
                 const float* __restrict__ bhn, const float* __restrict__ bon,
                 float* out)
{
    extern __shared__ char smem[];
    const int rowBase = blockIdx.y * BM;
    const __half* W   = (rowBase < NH) ? Wn  : Wn + (size_t)2 * DD * DD;
    const float* bias = (rowBase < NH) ? bhn : bon;
    gemm_body<false>(smem, threadIdx.x, g_nfh, g_zh, W, 2 * DD, 2 * DD,
                     rowBase, blockIdx.x * BN, out, nullptr, bias);
}

// ---------------------------------------------------------------------------
// warp-per-edge logits; fp16 A/B reads, fp32 math
__global__ __launch_bounds__(256)
void k_edge_logit(const int* __restrict__ src, const int* __restrict__ dst,
                  const float* __restrict__ b_hh, const float* __restrict__ b_oo,
                  const float* __restrict__ b_ho,
                  const float* __restrict__ W_a, const float* __restrict__ b_a)
{
    const int warp = threadIdx.x >> 5, lane = threadIdx.x & 31;
    const int e = blockIdx.x * 8 + warp;
    const int t = (e < EHH) ? 0 : (e < EHH + EOO ? 1 : 2);
    const float* bias = (t == 0) ? b_hh : (t == 1 ? b_oo : b_ho);
    const int s = src[e], d = dst[e];
    const uint4* Ar = (const uint4*)(g_Ah + ((size_t)t * NN + s) * DD);
    const uint4* Br = (const uint4*)(g_Bh + ((size_t)t * NN + d) * DD);

    float acc = 0.f;
#pragma unroll
    for (int i = 0; i < 4; i++) {
        const int idx = i * 32 + lane;
        uint4 av = Ar[idx], bv = Br[idx];
        const __half2* ah = (const __half2*)&av;
        const __half2* bh = (const __half2*)&bv;
        const int c0 = idx * 8;
#pragma unroll
        for (int j = 0; j < 4; j++) {
            float2 fa = __half22float2(ah[j]);
            float2 fb = __half22float2(bh[j]);
            const int c = c0 + j * 2;
            acc += fmaxf(fa.x + fb.x + bias[c], 0.f) * W_a[c]
                 + fmaxf(fa.y + fb.y + bias[c + 1], 0.f) * W_a[c + 1];
        }
    }
#pragma unroll
    for (int o = 16; o; o >>= 1) acc += __shfl_down_sync(0xffffffffu, acc, o);
    if (lane == 0) {
        float ex = expf(acc + b_a[0]);
        g_ex[e] = ex;
        atomicAdd(&g_den[d], ex);
    }
}

// ---------------------------------------------------------------------------
// CSR gather: block per dst node; z_f[d] = (sum ex_e * n_f[src_e]) / den[d]
__global__ __launch_bounds__(256)
void k_gather(const int* __restrict__ src)
{
    const int d = blockIdx.x;
    const int beg = g_off[d], end = g_off[d + 1];
    const int tid = threadIdx.x;
    __shared__ int   ss[256];
    __shared__ float sa[256];
    float4 acc = {0.f, 0.f, 0.f, 0.f};

    for (int base = beg; base < end; base += 256) {
        const int n = min(256, end - base);
        if (tid < n) {
            const int e = g_eid[base + tid];
            ss[tid] = src[e];
            sa[tid] = g_ex[e];
        }
        __syncthreads();
        for (int j = 0; j < n; j++) {
            const int s = ss[j];
            const float al = sa[j];
            uint2 hv = *(const uint2*)(g_nfh + (size_t)s * DD + tid * 4);
            float2 f0 = __half22float2(*(const __half2*)&hv.x);
            float2 f1 = __half22float2(*(const __half2*)&hv.y);
            acc.x += al * f0.x; acc.y += al * f0.y;
            acc.z += al * f1.x; acc.w += al * f1.y;
        }
        __syncthreads();
    }
    const float inv = (end > beg) ? 1.f / g_den[d] : 0.f;
    uint2 o;
    *(__half2*)&o.x = __floats2half2_rn(acc.x * inv, acc.y * inv);
    *(__half2*)&o.y = __floats2half2_rn(acc.z * inv, acc.w * inv);
    *(uint2*)(g_zh + (size_t)d * DD + tid * 4) = o;
}

// ---------------------------------------------------------------------------
extern "C" void kernel_launch(void* const* d_in, const int* in_sizes, int n_in,
                              void* d_out, int out_size)
{
    const float* n_f  = (const float*)d_in[0];
    const float* W_hh = (const float*)d_in[1];
    const float* b_hh = (const float*)d_in[2];
    const float* W_oo = (const float*)d_in[3];
    const float* b_oo = (const float*)d_in[4];
    const float* W_ho = (const float*)d_in[5];
    const float* b_ho = (const float*)d_in[6];
    const float* W_a  = (const float*)d_in[7];
    const float* b_a  = (const float*)d_in[8];
    const float* W_hn = (const float*)d_in[9];
    const float* b_hn = (const float*)d_in[10];
    const float* W_on = (const float*)d_in[11];
    const float* b_on = (const float*)d_in[12];
    const int*   esrc = (const int*)d_in[13];
    const int*   edst = (const int*)d_in[14];
    float* out = (float*)d_out;

    __half *gWp, *gWn;
    cudaGetSymbolAddress((void**)&gWp, g_Wp);
    cudaGetSymbolAddress((void**)&gWn, g_Wn);

    cudaFuncSetAttribute(k_gemm_proj, cudaFuncAttributeMaxDynamicSharedMemorySize, DYN_SMEM);
    cudaFuncSetAttribute(k_gemm_node, cudaFuncAttributeMaxDynamicSharedMemorySize, DYN_SMEM);

    k_zero<<<(NN + 256) / 256, 256>>>();
    k_cvt_nf<<<(NN * DD / 4) / 256, 256>>>(n_f);

    Ptr6 wp;
    wp.p[0] = W_hh; wp.p[1] = W_hh + (size_t)DD * DD;
    wp.p[2] = W_oo; wp.p[3] = W_oo + (size_t)DD * DD;
    wp.p[4] = W_ho; wp.p[5] = W_ho + (size_t)DD * DD;
    Ptr6 wn;
    wn.p[0] = W_hn; wn.p[1] = W_on;
    dim3 tb(32, 8);
    k_transpose6<<<dim3(32, 32, 6), tb>>>(wp, gWp, DD, DD, (size_t)DD * DD);
    k_transpose6<<<dim3(64, 32, 2), tb>>>(wn, gWn, 2 * DD, DD, (size_t)2 * DD * DD);

    // CSR build
    k_count<<<EE / 256, 256>>>(edst);
    k_scan<<<1, 1024>>>();
    k_fill<<<EE / 256, 256>>>(edst);

    // 6 projection GEMMs in one launch (z-dim selects weight)
    k_gemm_proj<<<dim3(DD / BN, NN / BM, 6), 256, DYN_SMEM>>>(gWp);

    k_edge_logit<<<EE / 8, 256>>>(esrc, edst, b_hh, b_oo, b_ho, W_a, b_a);
    k_gather<<<NN, 256>>>(esrc);

    k_gemm_node<<<dim3(DD / BN, NN / BM), 256, DYN_SMEM>>>(gWn, b_hn, b_on, out);
}

// round 17
// speedup vs baseline: 1.5682x; 1.2571x over previous
#include <cuda_runtime.h>
#include <cuda_fp16.h>
#include <cstdint>

#define NH   4096
#define NN   16384
#define DD   1024
#define EHH  8192
#define EOO  40960
#define EE   65536

// ---------------- GEMM tile config (fp16 mma.sync m16n8k16 + ldmatrix) -----
#define BM      128
#define BN      128
#define BK      64                            // halfs per k-chunk (128 B rows)
#define STAGES  3
#define LDPH    (BK + 8)                      // padded row stride in halfs (144 B)
#define STAGE_BYTES ((BM + BN) * LDPH * 2)    // 36864
#define DYN_SMEM (STAGES * STAGE_BYTES)       // 110592

// ---------------- scratch (__device__ globals; no allocs allowed) ----------
__device__ __half g_Ah[(size_t)3 * NN * DD];     // A_t compact rows (fp16)
__device__ __half g_Bh[(size_t)3 * NN * DD];     // B_t compact rows (fp16)
__device__ __half g_nfh[(size_t)NN * DD];        // fp16 copy of n_f
__device__ __half g_zh[(size_t)NN * DD];         // fp16 z_f
__device__ float  g_ex[EE];                      // exp(logit)
__device__ float  g_den[NN];                     // softmax denominators
__device__ __half g_Wp[(size_t)6 * DD * DD];     // 6 proj weights, [N,K], fp16
__device__ __half g_Wn[(size_t)2 * DD * 2 * DD]; // 2 node weights, [N,2K], fp16
__device__ int    g_off[NN + 1];                 // CSR offsets (by dst)
__device__ int    g_cnt[NN];                     // fill cursors
__device__ int    g_eid[EE];                     // CSR edge ids
__device__ int    g_map[6 * NN];                 // node -> compact idx+1 (0 = unused)
__device__ int    g_rows[6 * NN];                // compact idx -> node
__device__ int    g_mcnt[6];                     // compact counts

// ---------------- helpers ---------------------------------------------------
__device__ __forceinline__ uint32_t smem_u32(const void* p) {
    uint32_t a;
    asm("{ .reg .u64 t; cvta.to.shared.u64 t, %1; cvt.u32.u64 %0, t; }"
        : "=r"(a) : "l"(p));
    return a;
}
__device__ __forceinline__ void cp_async16(uint32_t dst, const void* src) {
    asm volatile("cp.async.cg.shared.global [%0], [%1], 16;"
                 :: "r"(dst), "l"(src) : "memory");
}
#define CP_COMMIT()  asm volatile("cp.async.commit_group;" ::: "memory")
#define CP_WAIT1()   asm volatile("cp.async.wait_group 1;" ::: "memory")

__device__ __forceinline__ void mma16(float* c, const uint32_t* a, const uint32_t* b) {
    asm volatile(
        "mma.sync.aligned.m16n8k16.row.col.f32.f16.f16.f32 "
        "{%0,%1,%2,%3}, {%4,%5,%6,%7}, {%8,%9}, {%0,%1,%2,%3};"
        : "+f"(c[0]), "+f"(c[1]), "+f"(c[2]), "+f"(c[3])
        : "r"(a[0]), "r"(a[1]), "r"(a[2]), "r"(a[3]), "r"(b[0]), "r"(b[1]));
}
__device__ __forceinline__ void ldm_x4(uint32_t* r, uint32_t addr) {
    asm volatile("ldmatrix.sync.aligned.m8n8.x4.shared.b16 {%0,%1,%2,%3}, [%4];"
                 : "=r"(r[0]), "=r"(r[1]), "=r"(r[2]), "=r"(r[3]) : "r"(addr));
}

// ---------------------------------------------------------------------------
__global__ void k_zero() {
    int i = blockIdx.x * blockDim.x + threadIdx.x;
    if (i < 6 * NN) g_map[i] = 0;
    if (i < NN) { g_den[i] = 0.f; g_cnt[i] = 0; }
    if (i <= NN) g_off[i] = 0;
}

// convert n_f -> g_nfh (fp16)
__global__ void k_cvt_nf(const float* __restrict__ src) {
    size_t i = (size_t)blockIdx.x * blockDim.x + threadIdx.x;
    float4 v = ((const float4*)src)[i];
    ((__half2*)g_nfh)[i * 2]     = __floats2half2_rn(v.x, v.y);
    ((__half2*)g_nfh)[i * 2 + 1] = __floats2half2_rn(v.z, v.w);
}

// flag nodes used per (type, side)
__global__ void k_flag(const int* __restrict__ src, const int* __restrict__ dst) {
    int e = blockIdx.x * blockDim.x + threadIdx.x;
    const int t = (e < EHH) ? 0 : (e < EHH + EOO ? 1 : 2);
    g_map[(2 * t) * NN + src[e]] = 1;
    g_map[(2 * t + 1) * NN + dst[e]] = 1;
}

// per-list compaction scan: blockIdx.x = list l in [0,6)
__global__ __launch_bounds__(1024) void k_scan6() {
    __shared__ int part[1024];
    const int l = blockIdx.x, tid = threadIdx.x;
    const int base = l * NN + tid * 16;
    int v[16], s = 0;
#pragma unroll
    for (int i = 0; i < 16; i++) { v[i] = g_map[base + i]; s += v[i]; }
    part[tid] = s;
    __syncthreads();
    for (int off = 1; off < 1024; off <<= 1) {
        int t = (tid >= off) ? part[tid - off] : 0;
        __syncthreads();
        part[tid] += t;
        __syncthreads();
    }
    int run = (tid == 0) ? 0 : part[tid - 1];
#pragma unroll
    for (int i = 0; i < 16; i++) {
        if (v[i]) {
            run++;
            g_map[base + i] = run;
            g_rows[l * NN + run - 1] = tid * 16 + i;
        } else {
            g_map[base + i] = 0;
        }
    }
    if (tid == 1023) g_mcnt[l] = part[1023];
}

// batched transpose + fp16 convert: dst[n*K + k] = half(src[k*Nn + n])
struct Ptr6 { const float* p[6]; };
__global__ void k_transpose6(const Ptr6 srcs, __half* __restrict__ dst0,
                             int K, int Nn, size_t slab) {
    __shared__ float t[32][33];
    const float* src = srcs.p[blockIdx.z];
    __half* dst = dst0 + slab * blockIdx.z;
    const int k0 = blockIdx.x * 32, n0 = blockIdx.y * 32;
    const int x = threadIdx.x, y = threadIdx.y;
#pragma unroll
    for (int i = y; i < 32; i += 8)
        t[i][x] = src[(size_t)(k0 + i) * Nn + n0 + x];
    __syncthreads();
#pragma unroll
    for (int i = y; i < 32; i += 8)
        dst[(size_t)(n0 + i) * K + k0 + x] = __float2half_rn(t[x][i]);
}

// ---------------- CSR build ------------------------------------------------
__global__ void k_count(const int* __restrict__ dst) {
    int e = blockIdx.x * blockDim.x + threadIdx.x;
    atomicAdd(&g_off[dst[e] + 1], 1);
}
__global__ __launch_bounds__(1024) void k_scan() {
    __shared__ int part[1024];
    const int tid = threadIdx.x;
    int v[16], s = 0;
#pragma unroll
    for (int i = 0; i < 16; i++) { v[i] = g_off[1 + tid * 16 + i]; s += v[i]; }
    part[tid] = s;
    __syncthreads();
    for (int off = 1; off < 1024; off <<= 1) {
        int t = (tid >= off) ? part[tid - off] : 0;
        __syncthreads();
        part[tid] += t;
        __syncthreads();
    }
    int run = (tid == 0) ? 0 : part[tid - 1];
#pragma unroll
    for (int i = 0; i < 16; i++) { run += v[i]; g_off[1 + tid * 16 + i] = run; }
}
__global__ void k_fill(const int* __restrict__ dst) {
    int e = blockIdx.x * blockDim.x + threadIdx.x;
    int d = dst[e];
    int pos = g_off[d] + atomicAdd(&g_cnt[d], 1);
    g_eid[pos] = e;
}

// ---------------------------------------------------------------------------
// fp16 mma.sync GEMM with ldmatrix fragment loads.
// 8 warps in 4(M) x 2(N); warp tile 32x64. BK=64 halfs per stage.
// rowIdx != nullptr: A rows gathered via rowIdx (clamped to [0, cnt-1]).
template <bool HALF_OUT>
__device__ __forceinline__ void gemm_body(
    char* smem, int tid,
    const __half* A0, const __half* A1, const __half* W, int ldB, int K,
    int rowBase, int colBase, float* outf, __half* outh,
    const float* bias, const int* rowIdx, int cnt)
{
    const int lane = tid & 31, wid = tid >> 5;
    const int grp = lane >> 2, t4 = lane & 3;
    const int wm = wid >> 1, wn = wid & 1;

    const uint32_t sb = smem_u32(smem);
    const int r = tid & 127;
    const bool isB = tid >= 128;
    const int KT = K / BK;

    int aRow = rowBase + r;
    if (rowIdx) aRow = __ldg(rowIdx + max(0, min(rowBase + r, cnt - 1)));

    // ldmatrix per-lane byte offsets within a stage
    const int l7 = lane & 7, l8 = (lane >> 3) & 1, l16 = (lane >> 4) & 1;
    uint32_t aOff[2], bOff[4];
#pragma unroll
    for (int mi = 0; mi < 2; mi++)
        aOff[mi] = (uint32_t)((wm * 32 + mi * 16 + l7 + l8 * 8) * LDPH + l16 * 8) * 2;
#pragma unroll
    for (int p = 0; p < 4; p++)
        bOff[p] = (uint32_t)((BM + wn * 64 + p * 16 + l16 * 8 + l7) * LDPH + l8 * 8) * 2;

    auto prefetch = [&](int st, int kt) {
        const int k0 = kt * BK;
        const uint32_t dbase = sb + st * STAGE_BYTES
                             + (uint32_t)((isB ? BM + r : r) * LDPH) * 2;
        const __half* gsrc;
        if (isB) {
            gsrc = W + (size_t)(colBase + r) * ldB + k0;
        } else {
            const __half* Asrc = (k0 < DD) ? A0 : A1;
            const int kk = (k0 < DD) ? k0 : k0 - DD;
            gsrc = Asrc + (size_t)aRow * DD + kk;
        }
#pragma unroll
        for (int i = 0; i < 8; i++)
            cp_async16(dbase + i * 16, gsrc + i * 8);
        CP_COMMIT();
    };

    prefetch(0, 0);
    prefetch(1, 1);

    float acc[2][8][4] = {};

    for (int kt = 0; kt < KT; kt++) {
        CP_WAIT1();
        __syncthreads();
        if (kt + 2 < KT) prefetch((kt + 2) % STAGES, kt + 2);
        else CP_COMMIT();

        const uint32_t stBase = sb + (uint32_t)((kt % STAGES) * STAGE_BYTES);

#pragma unroll
        for (int ks = 0; ks < 4; ks++) {
            const uint32_t kbb = ks * 32;          // 16 halfs = 32 bytes
            uint32_t a[2][4], b[4][4];
#pragma unroll
            for (int mi = 0; mi < 2; mi++)
                ldm_x4(a[mi], stBase + aOff[mi] + kbb);
#pragma unroll
            for (int p = 0; p < 4; p++)
                ldm_x4(b[p], stBase + bOff[p] + kbb);
#pragma unroll
            for (int mi = 0; mi < 2; mi++)
#pragma unroll
                for (int p = 0; p < 4; p++) {
                    mma16(acc[mi][2 * p],     a[mi], &b[p][0]);
                    mma16(acc[mi][2 * p + 1], a[mi], &b[p][2]);
                }
        }
    }

#pragma unroll
    for (int mi = 0; mi < 2; mi++) {
#pragma unroll
        for (int ni = 0; ni < 8; ni++) {
            const int row = rowBase + wm * 32 + mi * 16 + grp;
            const int col = colBase + wn * 64 + ni * 8 + t4 * 2;
            if (HALF_OUT) {
                *(__half2*)(outh + (size_t)row * DD + col) =
                    __floats2half2_rn(acc[mi][ni][0], acc[mi][ni][1]);
                *(__half2*)(outh + (size_t)(row + 8) * DD + col) =
                    __floats2half2_rn(acc[mi][ni][2], acc[mi][ni][3]);
            } else {
                const float b0 = bias[col], b1 = bias[col + 1];
                float2 v0 = {fmaxf(acc[mi][ni][0] + b0, 0.f),
                             fmaxf(acc[mi][ni][1] + b1, 0.f)};
                float2 v1 = {fmaxf(acc[mi][ni][2] + b0, 0.f),
                             fmaxf(acc[mi][ni][3] + b1, 0.f)};
                *(float2*)(outf + (size_t)row * DD + col) = v0;
                *(float2*)(outf + (size_t)(row + 8) * DD + col) = v1;
            }
        }
    }
}

// Projection GEMMs on compacted rows: z = 2t+h selects list/weight/output.
__global__ __launch_bounds__(256, 2)
void k_gemm_proj(const __half* __restrict__ Wp)
{
    extern __shared__ char smem[];
    const int z = blockIdx.z;
    const int cnt = g_mcnt[z];
    const int rowBase = blockIdx.y * BM;
    if (rowBase >= cnt) return;
    __half* outp = ((z & 1) ? g_Bh : g_Ah) + (size_t)(z >> 1) * NN * DD;
    gemm_body<true>(smem, threadIdx.x, g_nfh, g_nfh, Wp + (size_t)z * DD * DD,
                    DD, DD, rowBase, blockIdx.x * BN,
                    nullptr, outp, nullptr, g_rows + (size_t)z * NN, cnt);
}

// Node apply: A = [g_nfh | g_zh] (K=2048), W per node type, bias+relu, fp32 out.
__global__ __launch_bounds__(256, 2)
void k_gemm_node(const __half* __restrict__ Wn,
                 const float* __restrict__ bhn, const float* __restrict__ bon,
                 float* out)
{
    extern __shared__ char smem[];
    const int rowBase = blockIdx.y * BM;
    const __half* W   = (rowBase < NH) ? Wn  : Wn + (size_t)2 * DD * DD;
    const float* bias = (rowBase < NH) ? bhn : bon;
    gemm_body<false>(smem, threadIdx.x, g_nfh, g_zh, W, 2 * DD, 2 * DD,
                     rowBase, blockIdx.x * BN, out, nullptr, bias, nullptr, 0);
}

// ---------------------------------------------------------------------------
// warp-per-edge logits; compact fp16 A/B reads, fp32 math
__global__ __launch_bounds__(256)
void k_edge_logit(const int* __restrict__ src, const int* __restrict__ dst,
                  const float* __restrict__ b_hh, const float* __restrict__ b_oo,
                  const float* __restrict__ b_ho,
                  const float* __restrict__ W_a, const float* __restrict__ b_a)
{
    const int warp = threadIdx.x >> 5, lane = threadIdx.x & 31;
    const int e = blockIdx.x * 8 + warp;
    const int t = (e < EHH) ? 0 : (e < EHH + EOO ? 1 : 2);
    const float* bias = (t == 0) ? b_hh : (t == 1 ? b_oo : b_ho);
    const int s = src[e], d = dst[e];
    const int ai = __ldg(&g_map[(2 * t) * NN + s]) - 1;
    const int bi = __ldg(&g_map[(2 * t + 1) * NN + d]) - 1;
    const uint4* Ar = (const uint4*)(g_Ah + ((size_t)t * NN + ai) * DD);
    const uint4* Br = (const uint4*)(g_Bh + ((size_t)t * NN + bi) * DD);

    float acc = 0.f;
#pragma unroll
    for (int i = 0; i < 4; i++) {
        const int idx = i * 32 + lane;
        uint4 av = Ar[idx], bv = Br[idx];
        const __half2* ah = (const __half2*)&av;
        const __half2* bh = (const __half2*)&bv;
        const int c0 = idx * 8;
#pragma unroll
        for (int j = 0; j < 4; j++) {
            float2 fa = __half22float2(ah[j]);
            float2 fb = __half22float2(bh[j]);
            const int c = c0 + j * 2;
            acc += fmaxf(fa.x + fb.x + bias[c], 0.f) * W_a[c]
                 + fmaxf(fa.y + fb.y + bias[c + 1], 0.f) * W_a[c + 1];
        }
    }
#pragma unroll
    for (int o = 16; o; o >>= 1) acc += __shfl_down_sync(0xffffffffu, acc, o);
    if (lane == 0) {
        float ex = expf(acc + b_a[0]);
        g_ex[e] = ex;
        atomicAdd(&g_den[d], ex);
    }
}

// ---------------------------------------------------------------------------
// CSR gather: block per dst node; z_f[d] = (sum ex_e * n_f[src_e]) / den[d]
__global__ __launch_bounds__(256)
void k_gather(const int* __restrict__ src)
{
    const int d = blockIdx.x;
    const int beg = g_off[d], end = g_off[d + 1];
    const int tid = threadIdx.x;
    __shared__ int   ss[256];
    __shared__ float sa[256];
    float4 acc = {0.f, 0.f, 0.f, 0.f};

    for (int base = beg; base < end; base += 256) {
        const int n = min(256, end - base);
        if (tid < n) {
            const int e = g_eid[base + tid];
            ss[tid] = src[e];
            sa[tid] = g_ex[e];
        }
        __syncthreads();
        for (int j = 0; j < n; j++) {
            const int s = ss[j];
            const float al = sa[j];
            uint2 hv = *(const uint2*)(g_nfh + (size_t)s * DD + tid * 4);
            float2 f0 = __half22float2(*(const __half2*)&hv.x);
            float2 f1 = __half22float2(*(const __half2*)&hv.y);
            acc.x += al * f0.x; acc.y += al * f0.y;
            acc.z += al * f1.x; acc.w += al * f1.y;
        }
        __syncthreads();
    }
    const float inv = (end > beg) ? 1.f / g_den[d] : 0.f;
    uint2 o;
    *(__half2*)&o.x = __floats2half2_rn(acc.x * inv, acc.y * inv);
    *(__half2*)&o.y = __floats2half2_rn(acc.z * inv, acc.w * inv);
    *(uint2*)(g_zh + (size_t)d * DD + tid * 4) = o;
}

// ---------------------------------------------------------------------------
extern "C" void kernel_launch(void* const* d_in, const int* in_sizes, int n_in,
                              void* d_out, int out_size)
{
    const float* n_f  = (const float*)d_in[0];
    const float* W_hh = (const float*)d_in[1];
    const float* b_hh = (const float*)d_in[2];
    const float* W_oo = (const float*)d_in[3];
    const float* b_oo = (const float*)d_in[4];
    const float* W_ho = (const float*)d_in[5];
    const float* b_ho = (const float*)d_in[6];
    const float* W_a  = (const float*)d_in[7];
    const float* b_a  = (const float*)d_in[8];
    const float* W_hn = (const float*)d_in[9];
    const float* b_hn = (const float*)d_in[10];
    const float* W_on = (const float*)d_in[11];
    const float* b_on = (const float*)d_in[12];
    const int*   esrc = (const int*)d_in[13];
    const int*   edst = (const int*)d_in[14];
    float* out = (float*)d_out;

    __half *gWp, *gWn;
    cudaGetSymbolAddress((void**)&gWp, g_Wp);
    cudaGetSymbolAddress((void**)&gWn, g_Wn);

    cudaFuncSetAttribute(k_gemm_proj, cudaFuncAttributeMaxDynamicSharedMemorySize, DYN_SMEM);
    cudaFuncSetAttribute(k_gemm_node, cudaFuncAttributeMaxDynamicSharedMemorySize, DYN_SMEM);

    k_zero<<<(6 * NN) / 256, 256>>>();
    k_cvt_nf<<<(NN * DD / 4) / 256, 256>>>(n_f);
    k_flag<<<EE / 256, 256>>>(esrc, edst);
    k_scan6<<<6, 1024>>>();

    Ptr6 wp;
    wp.p[0] = W_hh; wp.p[1] = W_hh + (size_t)DD * DD;
    wp.p[2] = W_oo; wp.p[3] = W_oo + (size_t)DD * DD;
    wp.p[4] = W_ho; wp.p[5] = W_ho + (size_t)DD * DD;
    Ptr6 wn;
    wn.p[0] = W_hn; wn.p[1] = W_on;
    dim3 tb(32, 8);
    k_transpose6<<<dim3(32, 32, 6), tb>>>(wp, gWp, DD, DD, (size_t)DD * DD);
    k_transpose6<<<dim3(64, 32, 2), tb>>>(wn, gWn, 2 * DD, DD, (size_t)2 * DD * DD);

    // CSR build
    k_count<<<EE / 256, 256>>>(edst);
    k_scan<<<1, 1024>>>();
    k_fill<<<EE / 256, 256>>>(edst);

    // 6 projection GEMMs on compacted row sets (early-exit beyond counts)
    k_gemm_proj<<<dim3(DD / BN, NN / BM, 6), 256, DYN_SMEM>>>(gWp);

    k_edge_logit<<<EE / 8, 256>>>(esrc, edst, b_hh, b_oo, b_ho, W_a, b_a);
    k_gather<<<NN, 256>>>(esrc);

    k_gemm_node<<<dim3(DD / BN, NN / BM), 256, DYN_SMEM>>>(gWn, b_hn, b_on, out);
}